// round 3
// baseline (speedup 1.0000x reference)
#include <cuda_runtime.h>
#include <cstddef>

// Problem constants
#define BATCH 2
#define SEQ   2048
#define DMODEL 1024
#define NHEAD 16
#define DHEAD 64
#define MROWS (BATCH * SEQ)          // 4096
#define NQKV  (3 * NHEAD * DHEAD)    // 3072
#define OUT_ELEMS (MROWS * DMODEL)   // 4194304

// Scratch (device globals — no allocation allowed)
__device__ __align__(16) float g_qkv[(size_t)MROWS * NQKV];
__device__ __align__(16) float g_att[(size_t)MROWS * DMODEL];

#define FMA16(acc, a, b) \
  acc[0][0] += a.x*b.x; acc[0][1] += a.x*b.y; acc[0][2] += a.x*b.z; acc[0][3] += a.x*b.w; \
  acc[1][0] += a.y*b.x; acc[1][1] += a.y*b.y; acc[1][2] += a.y*b.z; acc[1][3] += a.y*b.w; \
  acc[2][0] += a.z*b.x; acc[2][1] += a.z*b.y; acc[2][2] += a.z*b.z; acc[2][3] += a.z*b.w; \
  acc[3][0] += a.w*b.x; acc[3][1] += a.w*b.y; acc[3][2] += a.w*b.z; acc[3][3] += a.w*b.w;

// ---------------------------------------------------------------------------
// GEMM: C[M,N] = A[M,K] @ B[K,N] + bias   (64x64 tile, 4x4 per thread, BK=16)
// kv_out != nullptr => QKV gemm: also scatter cols [1024,3072) into k/v output
// ---------------------------------------------------------------------------
__global__ __launch_bounds__(256)
void gemm_bias_kernel(const float* __restrict__ A, const float* __restrict__ B,
                      const float* __restrict__ bias, float* __restrict__ C,
                      int K, int N, float* __restrict__ kv_out)
{
    __shared__ float As[16][68];   // A^T tile: [k][m]
    __shared__ float Bs[16][68];   // B tile:   [k][n]
    const int tid = threadIdx.x;
    const int tx = tid & 15, ty = tid >> 4;
    const int bm = blockIdx.y * 64, bn = blockIdx.x * 64;

    const int ar = tid >> 2;            // row in A tile (0..63)
    const int ac = (tid & 3) << 2;      // k-quad in A tile
    const int br = tid >> 4;            // k row in B tile (0..15)
    const int bc = (tid & 15) << 2;     // n-quad in B tile

    const float* Aptr = A + (size_t)(bm + ar) * K + ac;
    const float* Bptr = B + (size_t)br * N + bn + bc;

    float acc[4][4] = {};
    for (int k0 = 0; k0 < K; k0 += 16) {
        float4 av = *(const float4*)(Aptr + k0);
        float4 bv = *(const float4*)(Bptr + (size_t)k0 * N);
        As[ac + 0][ar] = av.x; As[ac + 1][ar] = av.y;
        As[ac + 2][ar] = av.z; As[ac + 3][ar] = av.w;
        *(float4*)&Bs[br][bc] = bv;
        __syncthreads();
        #pragma unroll
        for (int kk = 0; kk < 16; kk++) {
            float4 a = *(const float4*)&As[kk][ty << 2];
            float4 b = *(const float4*)&Bs[kk][tx << 2];
            FMA16(acc, a, b)
        }
        __syncthreads();
    }

    const int n0 = bn + (tx << 2);
    float4 bb = *(const float4*)&bias[n0];
    #pragma unroll
    for (int i = 0; i < 4; i++) {
        const int row = bm + (ty << 2) + i;
        float4 c;
        c.x = acc[i][0] + bb.x; c.y = acc[i][1] + bb.y;
        c.z = acc[i][2] + bb.z; c.w = acc[i][3] + bb.w;
        *(float4*)&C[(size_t)row * N + n0] = c;
        if (kv_out) {
            if (n0 >= 2048)       // v slice
                *(float4*)&kv_out[(size_t)OUT_ELEMS + (size_t)row * DMODEL + (n0 - 2048)] = c;
            else if (n0 >= 1024)  // k slice
                *(float4*)&kv_out[(size_t)row * DMODEL + (n0 - 1024)] = c;
        }
    }
}

// ---------------------------------------------------------------------------
// Causal flash attention, fp32. Block = one (b, h, 64-row q-tile).
// smem: Q^T [d][r], KV buf (K^T [d][j] then V [j][c]), P^T [j][r]; stride 68.
// ---------------------------------------------------------------------------
#define FST 68
__global__ __launch_bounds__(256)
void flash_kernel(const float* __restrict__ qkv, float* __restrict__ out)
{
    extern __shared__ float sm[];
    float* Qts = sm;
    float* KVs = sm + 64 * FST;
    float* Pts = sm + 2 * 64 * FST;

    const int tid = threadIdx.x;
    const int tx = tid & 15, ty = tid >> 4;
    const int qt = (int)gridDim.x - 1 - (int)blockIdx.x;  // long blocks first
    const int h = blockIdx.y, b = blockIdx.z;
    const size_t rowbase = (size_t)b * SEQ;
    const int hq = h * DHEAD;

    const int lr = tid >> 2;       // 0..63 (row within tile for loads)
    const int lq = tid & 3;

    // Load Q^T, pre-scaled by 1/sqrt(Dh)
    {
        const float* qrow = qkv + (rowbase + qt * 64 + lr) * NQKV + hq;
        #pragma unroll
        for (int q = 0; q < 4; q++) {
            const int d0 = (lq + q * 4) * 4;
            float4 v = *(const float4*)(qrow + d0);
            Qts[(d0 + 0) * FST + lr] = v.x * 0.125f;
            Qts[(d0 + 1) * FST + lr] = v.y * 0.125f;
            Qts[(d0 + 2) * FST + lr] = v.z * 0.125f;
            Qts[(d0 + 3) * FST + lr] = v.w * 0.125f;
        }
    }

    float acc[4][4] = {};
    float m[4] = {-1e30f, -1e30f, -1e30f, -1e30f};
    float l[4] = {0.f, 0.f, 0.f, 0.f};

    for (int kt = 0; kt <= qt; kt++) {
        // K^T into KVs
        {
            const float* krow = qkv + (rowbase + kt * 64 + lr) * NQKV + 1024 + hq;
            #pragma unroll
            for (int q = 0; q < 4; q++) {
                const int d0 = (lq + q * 4) * 4;
                float4 v = *(const float4*)(krow + d0);
                KVs[(d0 + 0) * FST + lr] = v.x;
                KVs[(d0 + 1) * FST + lr] = v.y;
                KVs[(d0 + 2) * FST + lr] = v.z;
                KVs[(d0 + 3) * FST + lr] = v.w;
            }
        }
        __syncthreads();

        // S = Q K^T (4x4 per thread)
        float s[4][4] = {};
        #pragma unroll 16
        for (int d = 0; d < 64; d++) {
            float4 a = *(const float4*)&Qts[d * FST + (ty << 2)];
            float4 k = *(const float4*)&KVs[d * FST + (tx << 2)];
            FMA16(s, a, k)
        }
        __syncthreads();  // everyone done reading K^T

        // V into KVs (natural [j][c] layout)
        {
            const float* vrow = qkv + (rowbase + kt * 64 + lr) * NQKV + 2048 + hq;
            #pragma unroll
            for (int q = 0; q < 4; q++) {
                const int c0 = (lq + q * 4) * 4;
                *(float4*)&KVs[lr * FST + c0] = *(const float4*)(vrow + c0);
            }
        }

        // causal mask on the diagonal tile
        if (kt == qt) {
            #pragma unroll
            for (int i = 0; i < 4; i++)
                #pragma unroll
                for (int j = 0; j < 4; j++)
                    if ((tx << 2) + j > (ty << 2) + i) s[i][j] = -1e30f;
        }

        // online softmax (row reductions across the 16 tx lanes)
        #pragma unroll
        for (int i = 0; i < 4; i++) {
            float rm = fmaxf(fmaxf(s[i][0], s[i][1]), fmaxf(s[i][2], s[i][3]));
            rm = fmaxf(rm, __shfl_xor_sync(0xffffffffu, rm, 1, 16));
            rm = fmaxf(rm, __shfl_xor_sync(0xffffffffu, rm, 2, 16));
            rm = fmaxf(rm, __shfl_xor_sync(0xffffffffu, rm, 4, 16));
            rm = fmaxf(rm, __shfl_xor_sync(0xffffffffu, rm, 8, 16));
            const float mn = fmaxf(m[i], rm);
            const float sc = __expf(m[i] - mn);
            float rs = 0.f;
            #pragma unroll
            for (int j = 0; j < 4; j++) { s[i][j] = __expf(s[i][j] - mn); rs += s[i][j]; }
            rs += __shfl_xor_sync(0xffffffffu, rs, 1, 16);
            rs += __shfl_xor_sync(0xffffffffu, rs, 2, 16);
            rs += __shfl_xor_sync(0xffffffffu, rs, 4, 16);
            rs += __shfl_xor_sync(0xffffffffu, rs, 8, 16);
            l[i] = l[i] * sc + rs;
            m[i] = mn;
            #pragma unroll
            for (int j = 0; j < 4; j++) acc[i][j] *= sc;
        }

        // P^T to smem
        #pragma unroll
        for (int j = 0; j < 4; j++) {
            float4 pv = make_float4(s[0][j], s[1][j], s[2][j], s[3][j]);
            *(float4*)&Pts[((tx << 2) + j) * FST + (ty << 2)] = pv;
        }
        __syncthreads();  // V + P^T visible

        // O += P V
        #pragma unroll 16
        for (int j = 0; j < 64; j++) {
            float4 p = *(const float4*)&Pts[j * FST + (ty << 2)];
            float4 v = *(const float4*)&KVs[j * FST + (tx << 2)];
            FMA16(acc, p, v)
        }
        __syncthreads();  // before next tile overwrites KVs / Pts
    }

    // normalize + store
    #pragma unroll
    for (int i = 0; i < 4; i++) {
        const float inv = 1.0f / l[i];
        float4 o = make_float4(acc[i][0] * inv, acc[i][1] * inv,
                               acc[i][2] * inv, acc[i][3] * inv);
        const size_t row = rowbase + qt * 64 + (ty << 2) + i;
        *(float4*)&out[row * DMODEL + hq + (tx << 2)] = o;
    }
}

// ---------------------------------------------------------------------------
extern "C" void kernel_launch(void* const* d_in, const int* in_sizes, int n_in,
                              void* d_out, int out_size)
{
    const float* input = (const float*)d_in[0];
    // d_in[1] = mask (causal, hardcoded — ignored)
    const float* W_qkv = (const float*)d_in[2];
    const float* b_qkv = (const float*)d_in[3];
    const float* W_out = (const float*)d_in[4];
    const float* b_out = (const float*)d_in[5];
    float* out = (float*)d_out;

    float* qkv_ptr = nullptr;
    float* att_ptr = nullptr;
    cudaGetSymbolAddress((void**)&qkv_ptr, g_qkv);
    cudaGetSymbolAddress((void**)&att_ptr, g_att);

    // k/v slices go straight into the output if the output holds (out, k, v)
    float* kv_out = (out_size >= 3 * OUT_ELEMS) ? out + OUT_ELEMS : nullptr;

    // 1) QKV = input @ W_qkv + b_qkv  (epilogue scatters k, v)
    {
        dim3 grid(NQKV / 64, MROWS / 64);
        gemm_bias_kernel<<<grid, 256>>>(input, W_qkv, b_qkv, qkv_ptr,
                                        DMODEL, NQKV, kv_out);
    }

    // 2) causal flash attention
    {
        const int smem = 3 * 64 * FST * (int)sizeof(float);  // 52224 B
        cudaFuncSetAttribute(flash_kernel,
                             cudaFuncAttributeMaxDynamicSharedMemorySize, smem);
        dim3 grid(SEQ / 64, NHEAD, BATCH);
        flash_kernel<<<grid, 256, smem>>>(qkv_ptr, att_ptr);
    }

    // 3) out = att @ W_out + b_out
    {
        dim3 grid(DMODEL / 64, MROWS / 64);
        gemm_bias_kernel<<<grid, 256>>>(att_ptr, W_out, b_out, out,
                                        DMODEL, DMODEL, nullptr);
    }
}

// round 6
// speedup vs baseline: 1.5711x; 1.5711x over previous
#include <cuda_runtime.h>
#include <cuda_bf16.h>
#include <cstddef>
#include <cstdint>

// Problem constants
#define BATCH 2
#define SEQ   2048
#define DMODEL 1024
#define NHEAD 16
#define DHEAD 64
#define MROWS (BATCH * SEQ)          // 4096
#define NQKV  (3 * NHEAD * DHEAD)    // 3072
#define OUT_ELEMS (MROWS * DMODEL)   // 4194304

// Scratch (device globals — no allocation allowed)
__device__ __align__(16) float g_qkv[(size_t)MROWS * NQKV];
__device__ __align__(16) float g_att[(size_t)MROWS * DMODEL];
__device__ __align__(16) __nv_bfloat16 g_Ahi[(size_t)MROWS * DMODEL];
__device__ __align__(16) __nv_bfloat16 g_Alo[(size_t)MROWS * DMODEL];
__device__ __align__(16) __nv_bfloat16 g_Bhi[(size_t)NQKV * DMODEL];   // [N,K] transposed
__device__ __align__(16) __nv_bfloat16 g_Blo[(size_t)NQKV * DMODEL];

// ---------------------------------------------------------------------------
// Baseline-PTX helpers (sm_103 target — NO arch-specific 'a' features)
// ---------------------------------------------------------------------------
__device__ __forceinline__ uint32_t smem_u32(const void* p) {
    uint32_t a;
    asm("{ .reg .u64 t; cvta.to.shared.u64 t, %1; cvt.u32.u64 %0, t; }"
        : "=r"(a) : "l"(p));
    return a;
}
#define CPASYNC16(dst, src) \
    asm volatile("cp.async.cg.shared.global [%0], [%1], 16;" :: "r"(dst), "l"(src))
#define CPCOMMIT() asm volatile("cp.async.commit_group;" ::: "memory")

__device__ __forceinline__ void ldx4(uint32_t* r, uint32_t addr) {
    asm volatile("ldmatrix.sync.aligned.m8n8.x4.shared.b16 {%0,%1,%2,%3}, [%4];"
                 : "=r"(r[0]), "=r"(r[1]), "=r"(r[2]), "=r"(r[3]) : "r"(addr));
}
__device__ __forceinline__ void mma_bf16(float* c, const uint32_t* a,
                                         uint32_t b0, uint32_t b1) {
    asm volatile(
        "mma.sync.aligned.m16n8k16.row.col.f32.bf16.bf16.f32 "
        "{%0,%1,%2,%3}, {%4,%5,%6,%7}, {%8,%9}, {%0,%1,%2,%3};"
        : "+f"(c[0]), "+f"(c[1]), "+f"(c[2]), "+f"(c[3])
        : "r"(a[0]), "r"(a[1]), "r"(a[2]), "r"(a[3]), "r"(b0), "r"(b1));
}

// ---------------------------------------------------------------------------
// fp32 -> bf16 hi/lo split (elementwise)
// ---------------------------------------------------------------------------
__global__ void convert_hi_lo(const float* __restrict__ in,
                              __nv_bfloat16* __restrict__ hi,
                              __nv_bfloat16* __restrict__ lo, int n4)
{
    int i = blockIdx.x * blockDim.x + threadIdx.x;
    if (i >= n4) return;
    float4 v = ((const float4*)in)[i];
    __nv_bfloat16 h0 = __float2bfloat16(v.x), h1 = __float2bfloat16(v.y);
    __nv_bfloat16 h2 = __float2bfloat16(v.z), h3 = __float2bfloat16(v.w);
    __nv_bfloat162* H = (__nv_bfloat162*)hi;
    __nv_bfloat162* L = (__nv_bfloat162*)lo;
    H[2 * i]     = __halves2bfloat162(h0, h1);
    H[2 * i + 1] = __halves2bfloat162(h2, h3);
    L[2 * i]     = __halves2bfloat162(__float2bfloat16(v.x - __bfloat162float(h0)),
                                      __float2bfloat16(v.y - __bfloat162float(h1)));
    L[2 * i + 1] = __halves2bfloat162(__float2bfloat16(v.z - __bfloat162float(h2)),
                                      __float2bfloat16(v.w - __bfloat162float(h3)));
}

// W [K=1024, N] -> Wt hi/lo [N, 1024], tiled transpose + split
__global__ void convert_wt(const float* __restrict__ W,
                           __nv_bfloat16* __restrict__ hi,
                           __nv_bfloat16* __restrict__ lo, int N)
{
    __shared__ float t[32][33];
    const int nx = blockIdx.x * 32 + threadIdx.x;
    const int k0 = blockIdx.y * 32;
    #pragma unroll
    for (int j = 0; j < 4; j++)
        t[threadIdx.y + j * 8][threadIdx.x] = W[(size_t)(k0 + threadIdx.y + j * 8) * N + nx];
    __syncthreads();
    const int k = k0 + threadIdx.x;
    #pragma unroll
    for (int j = 0; j < 4; j++) {
        const int nrow = blockIdx.x * 32 + threadIdx.y + j * 8;
        float x = t[threadIdx.x][threadIdx.y + j * 8];
        __nv_bfloat16 h = __float2bfloat16(x);
        hi[(size_t)nrow * 1024 + k] = h;
        lo[(size_t)nrow * 1024 + k] = __float2bfloat16(x - __bfloat162float(h));
    }
}

// ---------------------------------------------------------------------------
// mma.sync split-bf16 GEMM: C[M,N] = A[M,1024] @ Bt[N,1024]^T + bias
// CTA 128x128, BK=32, 8 warps (2x4), warp tile 64x32, double-buffered cp.async.
// Products: Ahi*Bhi + Alo*Bhi + Ahi*Blo (fp32 accumulate).
// Smem tiles 128 rows x 40 bf16 (80B stride: conflict-free ldmatrix).
// ---------------------------------------------------------------------------
#define GK       1024
#define GBK      32
#define GNC      (GK / GBK)          // 32
#define TILE_B   (128 * 80)          // 10240 B per tile
#define STAGE_B  (4 * TILE_B)        // 40960 B
#define GM_SMEM  (2 * STAGE_B)       // 81920 B

__global__ __launch_bounds__(256, 1)
void gemm_mma(const __nv_bfloat16* __restrict__ Ahi, const __nv_bfloat16* __restrict__ Alo,
              const __nv_bfloat16* __restrict__ Bhi, const __nv_bfloat16* __restrict__ Blo,
              const float* __restrict__ bias, float* __restrict__ C,
              int N, float* __restrict__ kv_out)
{
    extern __shared__ __align__(128) char smg[];
    const uint32_t sb = smem_u32(smg);
    const int tid = threadIdx.x, wid = tid >> 5, lane = tid & 31;
    const int wm = wid & 1, wn = wid >> 1;           // 2 x 4 warp grid
    const int bm = blockIdx.y * 128, bn = blockIdx.x * 128;

    const __nv_bfloat16* srcp[4];
    srcp[0] = Ahi + (size_t)bm * GK;
    srcp[1] = Alo + (size_t)bm * GK;
    srcp[2] = Bhi + (size_t)bn * GK;
    srcp[3] = Blo + (size_t)bn * GK;

    auto load_stage = [&](int c, int s) {
        const int k0 = c * GBK;
        #pragma unroll
        for (int t = 0; t < 4; t++) {
            const uint32_t tb = sb + s * STAGE_B + t * TILE_B;
            const __nv_bfloat16* bp = srcp[t] + k0;
            #pragma unroll
            for (int i = 0; i < 2; i++) {
                const int idx = tid + i * 256;       // 0..511
                const int row = idx >> 2, q = idx & 3;
                CPASYNC16(tb + row * 80 + q * 16,
                          (const char*)(bp + (size_t)row * GK + q * 8));
            }
        }
        CPCOMMIT();
    };

    // ldmatrix lane addressing (within a stage/tile, byte offsets)
    const int a_row = (lane & 15);                   // + mf*16 + wm*64
    const int a_kb  = ((lane >> 4) << 3) * 2;        // + ks*32 bytes
    const int b_row = ((lane >> 4) << 3) + (lane & 7);  // + nf2*16 + wn*32
    const int b_kb  = (((lane >> 3) & 1) << 3) * 2;

    float acc[4][4][4];
    #pragma unroll
    for (int i = 0; i < 4; i++)
        #pragma unroll
        for (int j = 0; j < 4; j++)
            #pragma unroll
            for (int k = 0; k < 4; k++) acc[i][j][k] = 0.f;

    load_stage(0, 0);
    #pragma unroll 1
    for (int c = 0; c < GNC; c++) {
        const int s = c & 1;
        if (c + 1 < GNC) {
            load_stage(c + 1, s ^ 1);
            asm volatile("cp.async.wait_group 1;" ::: "memory");
        } else {
            asm volatile("cp.async.wait_group 0;" ::: "memory");
        }
        __syncthreads();

        const uint32_t st = sb + s * STAGE_B;
        #pragma unroll
        for (int ks = 0; ks < 2; ks++) {
            uint32_t ah[4][4], al[4][4], bh[2][4], bl[2][4];
            const uint32_t akb = ks * 32 + a_kb;
            const uint32_t bkb = ks * 32 + b_kb;
            #pragma unroll
            for (int mf = 0; mf < 4; mf++) {
                const uint32_t off = (uint32_t)(wm * 64 + mf * 16 + a_row) * 80 + akb;
                ldx4(ah[mf], st + 0 * TILE_B + off);
                ldx4(al[mf], st + 1 * TILE_B + off);
            }
            #pragma unroll
            for (int nf2 = 0; nf2 < 2; nf2++) {
                const uint32_t off = (uint32_t)(wn * 32 + nf2 * 16 + b_row) * 80 + bkb;
                ldx4(bh[nf2], st + 2 * TILE_B + off);
                ldx4(bl[nf2], st + 3 * TILE_B + off);
            }
            #pragma unroll
            for (int mf = 0; mf < 4; mf++)
                #pragma unroll
                for (int nf2 = 0; nf2 < 2; nf2++)
                    #pragma unroll
                    for (int j = 0; j < 2; j++) {
                        float* a4 = acc[mf][nf2 * 2 + j];
                        mma_bf16(a4, ah[mf], bh[nf2][2 * j], bh[nf2][2 * j + 1]);
                        mma_bf16(a4, al[mf], bh[nf2][2 * j], bh[nf2][2 * j + 1]);
                        mma_bf16(a4, ah[mf], bl[nf2][2 * j], bl[nf2][2 * j + 1]);
                    }
        }
        __syncthreads();
    }

    // Epilogue: fragment layout -> gmem. Thread holds rows gid, gid+8; cols 2*tig.
    const int gid = lane >> 2, tig = lane & 3;
    #pragma unroll
    for (int mf = 0; mf < 4; mf++) {
        #pragma unroll
        for (int nf = 0; nf < 4; nf++) {
            const int n = bn + wn * 32 + nf * 8 + 2 * tig;
            const float bx = bias[n], by = bias[n + 1];
            #pragma unroll
            for (int h = 0; h < 2; h++) {
                const int row = bm + wm * 64 + mf * 16 + gid + h * 8;
                float2 cv;
                cv.x = acc[mf][nf][2 * h + 0] + bx;
                cv.y = acc[mf][nf][2 * h + 1] + by;
                *(float2*)&C[(size_t)row * N + n] = cv;
                if (kv_out) {
                    if (n >= 2048)
                        *(float2*)&kv_out[(size_t)OUT_ELEMS + (size_t)row * DMODEL + (n - 2048)] = cv;
                    else if (n >= 1024)
                        *(float2*)&kv_out[(size_t)row * DMODEL + (n - 1024)] = cv;
                }
            }
        }
    }
}

// ---------------------------------------------------------------------------
// Causal flash attention, fp32 (unchanged from passing baseline)
// ---------------------------------------------------------------------------
#define FMA16(acc, a, b) \
  acc[0][0] += a.x*b.x; acc[0][1] += a.x*b.y; acc[0][2] += a.x*b.z; acc[0][3] += a.x*b.w; \
  acc[1][0] += a.y*b.x; acc[1][1] += a.y*b.y; acc[1][2] += a.y*b.z; acc[1][3] += a.y*b.w; \
  acc[2][0] += a.z*b.x; acc[2][1] += a.z*b.y; acc[2][2] += a.z*b.z; acc[2][3] += a.z*b.w; \
  acc[3][0] += a.w*b.x; acc[3][1] += a.w*b.y; acc[3][2] += a.w*b.z; acc[3][3] += a.w*b.w;

#define FST 68
__global__ __launch_bounds__(256)
void flash_kernel(const float* __restrict__ qkv, float* __restrict__ out)
{
    extern __shared__ float sm[];
    float* Qts = sm;
    float* KVs = sm + 64 * FST;
    float* Pts = sm + 2 * 64 * FST;

    const int tid = threadIdx.x;
    const int tx = tid & 15, ty = tid >> 4;
    const int qt = (int)gridDim.x - 1 - (int)blockIdx.x;
    const int h = blockIdx.y, b = blockIdx.z;
    const size_t rowbase = (size_t)b * SEQ;
    const int hq = h * DHEAD;

    const int lr = tid >> 2;
    const int lq = tid & 3;

    {
        const float* qrow = qkv + (rowbase + qt * 64 + lr) * NQKV + hq;
        #pragma unroll
        for (int q = 0; q < 4; q++) {
            const int d0 = (lq + q * 4) * 4;
            float4 v = *(const float4*)(qrow + d0);
            Qts[(d0 + 0) * FST + lr] = v.x * 0.125f;
            Qts[(d0 + 1) * FST + lr] = v.y * 0.125f;
            Qts[(d0 + 2) * FST + lr] = v.z * 0.125f;
            Qts[(d0 + 3) * FST + lr] = v.w * 0.125f;
        }
    }

    float acc[4][4] = {};
    float m[4] = {-1e30f, -1e30f, -1e30f, -1e30f};
    float l[4] = {0.f, 0.f, 0.f, 0.f};

    for (int kt = 0; kt <= qt; kt++) {
        {
            const float* krow = qkv + (rowbase + kt * 64 + lr) * NQKV + 1024 + hq;
            #pragma unroll
            for (int q = 0; q < 4; q++) {
                const int d0 = (lq + q * 4) * 4;
                float4 v = *(const float4*)(krow + d0);
                KVs[(d0 + 0) * FST + lr] = v.x;
                KVs[(d0 + 1) * FST + lr] = v.y;
                KVs[(d0 + 2) * FST + lr] = v.z;
                KVs[(d0 + 3) * FST + lr] = v.w;
            }
        }
        __syncthreads();

        float s[4][4] = {};
        #pragma unroll 16
        for (int d = 0; d < 64; d++) {
            float4 a = *(const float4*)&Qts[d * FST + (ty << 2)];
            float4 k = *(const float4*)&KVs[d * FST + (tx << 2)];
            FMA16(s, a, k)
        }
        __syncthreads();

        {
            const float* vrow = qkv + (rowbase + kt * 64 + lr) * NQKV + 2048 + hq;
            #pragma unroll
            for (int q = 0; q < 4; q++) {
                const int c0 = (lq + q * 4) * 4;
                *(float4*)&KVs[lr * FST + c0] = *(const float4*)(vrow + c0);
            }
        }

        if (kt == qt) {
            #pragma unroll
            for (int i = 0; i < 4; i++)
                #pragma unroll
                for (int j = 0; j < 4; j++)
                    if ((tx << 2) + j > (ty << 2) + i) s[i][j] = -1e30f;
        }

        #pragma unroll
        for (int i = 0; i < 4; i++) {
            float rm = fmaxf(fmaxf(s[i][0], s[i][1]), fmaxf(s[i][2], s[i][3]));
            rm = fmaxf(rm, __shfl_xor_sync(0xffffffffu, rm, 1, 16));
            rm = fmaxf(rm, __shfl_xor_sync(0xffffffffu, rm, 2, 16));
            rm = fmaxf(rm, __shfl_xor_sync(0xffffffffu, rm, 4, 16));
            rm = fmaxf(rm, __shfl_xor_sync(0xffffffffu, rm, 8, 16));
            const float mn = fmaxf(m[i], rm);
            const float sc = __expf(m[i] - mn);
            float rs = 0.f;
            #pragma unroll
            for (int j = 0; j < 4; j++) { s[i][j] = __expf(s[i][j] - mn); rs += s[i][j]; }
            rs += __shfl_xor_sync(0xffffffffu, rs, 1, 16);
            rs += __shfl_xor_sync(0xffffffffu, rs, 2, 16);
            rs += __shfl_xor_sync(0xffffffffu, rs, 4, 16);
            rs += __shfl_xor_sync(0xffffffffu, rs, 8, 16);
            l[i] = l[i] * sc + rs;
            m[i] = mn;
            #pragma unroll
            for (int j = 0; j < 4; j++) acc[i][j] *= sc;
        }

        #pragma unroll
        for (int j = 0; j < 4; j++) {
            float4 pv = make_float4(s[0][j], s[1][j], s[2][j], s[3][j]);
            *(float4*)&Pts[((tx << 2) + j) * FST + (ty << 2)] = pv;
        }
        __syncthreads();

        #pragma unroll 16
        for (int j = 0; j < 64; j++) {
            float4 p = *(const float4*)&Pts[j * FST + (ty << 2)];
            float4 v = *(const float4*)&KVs[j * FST + (tx << 2)];
            FMA16(acc, p, v)
        }
        __syncthreads();
    }

    #pragma unroll
    for (int i = 0; i < 4; i++) {
        const float inv = 1.0f / l[i];
        float4 o = make_float4(acc[i][0] * inv, acc[i][1] * inv,
                               acc[i][2] * inv, acc[i][3] * inv);
        const size_t row = rowbase + qt * 64 + (ty << 2) + i;
        *(float4*)&out[row * DMODEL + hq + (tx << 2)] = o;
    }
}

// ---------------------------------------------------------------------------
extern "C" void kernel_launch(void* const* d_in, const int* in_sizes, int n_in,
                              void* d_out, int out_size)
{
    const float* input = (const float*)d_in[0];
    // d_in[1] = mask (causal, hardcoded — ignored)
    const float* W_qkv = (const float*)d_in[2];
    const float* b_qkv = (const float*)d_in[3];
    const float* W_out = (const float*)d_in[4];
    const float* b_out = (const float*)d_in[5];
    float* out = (float*)d_out;

    float *qkv_ptr = nullptr, *att_ptr = nullptr;
    __nv_bfloat16 *ahi = nullptr, *alo = nullptr, *bhi = nullptr, *blo = nullptr;
    cudaGetSymbolAddress((void**)&qkv_ptr, g_qkv);
    cudaGetSymbolAddress((void**)&att_ptr, g_att);
    cudaGetSymbolAddress((void**)&ahi, g_Ahi);
    cudaGetSymbolAddress((void**)&alo, g_Alo);
    cudaGetSymbolAddress((void**)&bhi, g_Bhi);
    cudaGetSymbolAddress((void**)&blo, g_Blo);

    float* kv_out = (out_size >= 3 * OUT_ELEMS) ? out + OUT_ELEMS : nullptr;

    cudaFuncSetAttribute(gemm_mma, cudaFuncAttributeMaxDynamicSharedMemorySize, GM_SMEM);

    // 1) split input + W_qkv^T to bf16 hi/lo
    convert_hi_lo<<<(OUT_ELEMS / 4 + 255) / 256, 256>>>(input, ahi, alo, OUT_ELEMS / 4);
    convert_wt<<<dim3(NQKV / 32, DMODEL / 32), dim3(32, 8)>>>(W_qkv, bhi, blo, NQKV);

    // 2) QKV = input @ W_qkv + b_qkv  (epilogue scatters k, v)
    gemm_mma<<<dim3(NQKV / 128, MROWS / 128), 256, GM_SMEM>>>(
        ahi, alo, bhi, blo, b_qkv, qkv_ptr, NQKV, kv_out);

    // 3) causal flash attention
    {
        const int smem = 3 * 64 * FST * (int)sizeof(float);
        cudaFuncSetAttribute(flash_kernel,
                             cudaFuncAttributeMaxDynamicSharedMemorySize, smem);
        dim3 grid(SEQ / 64, NHEAD, BATCH);
        flash_kernel<<<grid, 256, smem>>>(qkv_ptr, att_ptr);
    }

    // 4) split att + W_out^T, then out = att @ W_out + b_out
    convert_hi_lo<<<(OUT_ELEMS / 4 + 255) / 256, 256>>>(att_ptr, ahi, alo, OUT_ELEMS / 4);
    convert_wt<<<dim3(DMODEL / 32, DMODEL / 32), dim3(32, 8)>>>(W_out, bhi, blo, DMODEL);
    gemm_mma<<<dim3(DMODEL / 128, MROWS / 128), 256, GM_SMEM>>>(
        ahi, alo, bhi, blo, b_out, out, DMODEL, nullptr);
}

// round 7
// speedup vs baseline: 2.9490x; 1.8771x over previous
#include <cuda_runtime.h>
#include <cuda_bf16.h>
#include <cuda_fp16.h>
#include <cstddef>
#include <cstdint>

// Problem constants
#define BATCH 2
#define SEQ   2048
#define DMODEL 1024
#define NHEAD 16
#define DHEAD 64
#define MROWS (BATCH * SEQ)          // 4096
#define NQKV  (3 * NHEAD * DHEAD)    // 3072
#define OUT_ELEMS (MROWS * DMODEL)   // 4194304

// Scratch (device globals — no allocation allowed)
__device__ __align__(16) float g_att[(size_t)MROWS * DMODEL];
__device__ __align__(16) __nv_bfloat16 g_Ahi[(size_t)MROWS * DMODEL];
__device__ __align__(16) __nv_bfloat16 g_Alo[(size_t)MROWS * DMODEL];
__device__ __align__(16) __nv_bfloat16 g_Bhi[(size_t)NQKV * DMODEL];   // [N,K] transposed
__device__ __align__(16) __nv_bfloat16 g_Blo[(size_t)NQKV * DMODEL];
__device__ __align__(16) __nv_bfloat16 g_qhi[(size_t)MROWS * DMODEL];
__device__ __align__(16) __nv_bfloat16 g_qlo[(size_t)MROWS * DMODEL];
__device__ __align__(16) __nv_bfloat16 g_khi[(size_t)MROWS * DMODEL];
__device__ __align__(16) __nv_bfloat16 g_klo[(size_t)MROWS * DMODEL];
__device__ __align__(16) __half        g_vh [(size_t)MROWS * DMODEL];

// ---------------------------------------------------------------------------
// Baseline-PTX helpers (sm_103 target — NO arch-specific 'a' features)
// ---------------------------------------------------------------------------
__device__ __forceinline__ uint32_t smem_u32(const void* p) {
    uint32_t a;
    asm("{ .reg .u64 t; cvta.to.shared.u64 t, %1; cvt.u32.u64 %0, t; }"
        : "=r"(a) : "l"(p));
    return a;
}
#define CPASYNC16(dst, src) \
    asm volatile("cp.async.cg.shared.global [%0], [%1], 16;" :: "r"(dst), "l"(src))
#define CPCOMMIT() asm volatile("cp.async.commit_group;" ::: "memory")

__device__ __forceinline__ void ldx4(uint32_t* r, uint32_t addr) {
    asm volatile("ldmatrix.sync.aligned.m8n8.x4.shared.b16 {%0,%1,%2,%3}, [%4];"
                 : "=r"(r[0]), "=r"(r[1]), "=r"(r[2]), "=r"(r[3]) : "r"(addr));
}
__device__ __forceinline__ void ldx4t(uint32_t* r, uint32_t addr) {
    asm volatile("ldmatrix.sync.aligned.m8n8.x4.trans.shared.b16 {%0,%1,%2,%3}, [%4];"
                 : "=r"(r[0]), "=r"(r[1]), "=r"(r[2]), "=r"(r[3]) : "r"(addr));
}
__device__ __forceinline__ void mma_bf16(float* c, const uint32_t* a,
                                         uint32_t b0, uint32_t b1) {
    asm volatile(
        "mma.sync.aligned.m16n8k16.row.col.f32.bf16.bf16.f32 "
        "{%0,%1,%2,%3}, {%4,%5,%6,%7}, {%8,%9}, {%0,%1,%2,%3};"
        : "+f"(c[0]), "+f"(c[1]), "+f"(c[2]), "+f"(c[3])
        : "r"(a[0]), "r"(a[1]), "r"(a[2]), "r"(a[3]), "r"(b0), "r"(b1));
}
__device__ __forceinline__ void mma_f16(float* c, const uint32_t* a,
                                        uint32_t b0, uint32_t b1) {
    asm volatile(
        "mma.sync.aligned.m16n8k16.row.col.f32.f16.f16.f32 "
        "{%0,%1,%2,%3}, {%4,%5,%6,%7}, {%8,%9}, {%0,%1,%2,%3};"
        : "+f"(c[0]), "+f"(c[1]), "+f"(c[2]), "+f"(c[3])
        : "r"(a[0]), "r"(a[1]), "r"(a[2]), "r"(a[3]), "r"(b0), "r"(b1));
}
// pack two f32 into f16x2: lo half = first arg
__device__ __forceinline__ uint32_t packh2(float lo, float hi) {
    uint32_t r;
    asm("cvt.rn.f16x2.f32 %0, %1, %2;" : "=r"(r) : "f"(hi), "f"(lo));
    return r;
}

// ---------------------------------------------------------------------------
// fp32 -> bf16 hi/lo split (elementwise)
// ---------------------------------------------------------------------------
__global__ void convert_hi_lo(const float* __restrict__ in,
                              __nv_bfloat16* __restrict__ hi,
                              __nv_bfloat16* __restrict__ lo, int n4)
{
    int i = blockIdx.x * blockDim.x + threadIdx.x;
    if (i >= n4) return;
    float4 v = ((const float4*)in)[i];
    __nv_bfloat16 h0 = __float2bfloat16(v.x), h1 = __float2bfloat16(v.y);
    __nv_bfloat16 h2 = __float2bfloat16(v.z), h3 = __float2bfloat16(v.w);
    __nv_bfloat162* H = (__nv_bfloat162*)hi;
    __nv_bfloat162* L = (__nv_bfloat162*)lo;
    H[2 * i]     = __halves2bfloat162(h0, h1);
    H[2 * i + 1] = __halves2bfloat162(h2, h3);
    L[2 * i]     = __halves2bfloat162(__float2bfloat16(v.x - __bfloat162float(h0)),
                                      __float2bfloat16(v.y - __bfloat162float(h1)));
    L[2 * i + 1] = __halves2bfloat162(__float2bfloat16(v.z - __bfloat162float(h2)),
                                      __float2bfloat16(v.w - __bfloat162float(h3)));
}

// W [K=1024, N] -> Wt hi/lo [N, 1024], tiled transpose + split
__global__ void convert_wt(const float* __restrict__ W,
                           __nv_bfloat16* __restrict__ hi,
                           __nv_bfloat16* __restrict__ lo, int N)
{
    __shared__ float t[32][33];
    const int nx = blockIdx.x * 32 + threadIdx.x;
    const int k0 = blockIdx.y * 32;
    #pragma unroll
    for (int j = 0; j < 4; j++)
        t[threadIdx.y + j * 8][threadIdx.x] = W[(size_t)(k0 + threadIdx.y + j * 8) * N + nx];
    __syncthreads();
    const int k = k0 + threadIdx.x;
    #pragma unroll
    for (int j = 0; j < 4; j++) {
        const int nrow = blockIdx.x * 32 + threadIdx.y + j * 8;
        float x = t[threadIdx.x][threadIdx.y + j * 8];
        __nv_bfloat16 h = __float2bfloat16(x);
        hi[(size_t)nrow * 1024 + k] = h;
        lo[(size_t)nrow * 1024 + k] = __float2bfloat16(x - __bfloat162float(h));
    }
}

// ---------------------------------------------------------------------------
// mma.sync split-bf16 GEMM: C[M,N] = A[M,1024] @ Bt[N,1024]^T + bias
// qkv_mode: instead of C, emit q (x0.125) / k as bf16 hi+lo, v as fp16,
// and k/v fp32 into kv_out.
// ---------------------------------------------------------------------------
#define GK       1024
#define GBK      32
#define GNC      (GK / GBK)          // 32
#define TILE_B   (128 * 80)          // 10240 B per tile
#define STAGE_B  (4 * TILE_B)        // 40960 B
#define GM_SMEM  (2 * STAGE_B)       // 81920 B

__global__ __launch_bounds__(256, 1)
void gemm_mma(const __nv_bfloat16* __restrict__ Ahi, const __nv_bfloat16* __restrict__ Alo,
              const __nv_bfloat16* __restrict__ Bhi, const __nv_bfloat16* __restrict__ Blo,
              const float* __restrict__ bias, float* __restrict__ C,
              int N, float* __restrict__ kv_out,
              __nv_bfloat16* __restrict__ qhi, __nv_bfloat16* __restrict__ qlo,
              __nv_bfloat16* __restrict__ khi, __nv_bfloat16* __restrict__ klo,
              __half* __restrict__ vh)
{
    extern __shared__ __align__(128) char smg[];
    const uint32_t sb = smem_u32(smg);
    const int tid = threadIdx.x, wid = tid >> 5, lane = tid & 31;
    const int wm = wid & 1, wn = wid >> 1;           // 2 x 4 warp grid
    const int bm = blockIdx.y * 128, bn = blockIdx.x * 128;

    const __nv_bfloat16* srcp[4];
    srcp[0] = Ahi + (size_t)bm * GK;
    srcp[1] = Alo + (size_t)bm * GK;
    srcp[2] = Bhi + (size_t)bn * GK;
    srcp[3] = Blo + (size_t)bn * GK;

    auto load_stage = [&](int c, int s) {
        const int k0 = c * GBK;
        #pragma unroll
        for (int t = 0; t < 4; t++) {
            const uint32_t tb = sb + s * STAGE_B + t * TILE_B;
            const __nv_bfloat16* bp = srcp[t] + k0;
            #pragma unroll
            for (int i = 0; i < 2; i++) {
                const int idx = tid + i * 256;       // 0..511
                const int row = idx >> 2, q = idx & 3;
                CPASYNC16(tb + row * 80 + q * 16,
                          (const char*)(bp + (size_t)row * GK + q * 8));
            }
        }
        CPCOMMIT();
    };

    const int a_row = (lane & 15);
    const int a_kb  = ((lane >> 4) << 3) * 2;
    const int b_row = ((lane >> 4) << 3) + (lane & 7);
    const int b_kb  = (((lane >> 3) & 1) << 3) * 2;

    float acc[4][4][4];
    #pragma unroll
    for (int i = 0; i < 4; i++)
        #pragma unroll
        for (int j = 0; j < 4; j++)
            #pragma unroll
            for (int k = 0; k < 4; k++) acc[i][j][k] = 0.f;

    load_stage(0, 0);
    #pragma unroll 1
    for (int c = 0; c < GNC; c++) {
        const int s = c & 1;
        if (c + 1 < GNC) {
            load_stage(c + 1, s ^ 1);
            asm volatile("cp.async.wait_group 1;" ::: "memory");
        } else {
            asm volatile("cp.async.wait_group 0;" ::: "memory");
        }
        __syncthreads();

        const uint32_t st = sb + s * STAGE_B;
        #pragma unroll
        for (int ks = 0; ks < 2; ks++) {
            uint32_t ah[4][4], al[4][4], bh[2][4], bl[2][4];
            const uint32_t akb = ks * 32 + a_kb;
            const uint32_t bkb = ks * 32 + b_kb;
            #pragma unroll
            for (int mf = 0; mf < 4; mf++) {
                const uint32_t off = (uint32_t)(wm * 64 + mf * 16 + a_row) * 80 + akb;
                ldx4(ah[mf], st + 0 * TILE_B + off);
                ldx4(al[mf], st + 1 * TILE_B + off);
            }
            #pragma unroll
            for (int nf2 = 0; nf2 < 2; nf2++) {
                const uint32_t off = (uint32_t)(wn * 32 + nf2 * 16 + b_row) * 80 + bkb;
                ldx4(bh[nf2], st + 2 * TILE_B + off);
                ldx4(bl[nf2], st + 3 * TILE_B + off);
            }
            #pragma unroll
            for (int mf = 0; mf < 4; mf++)
                #pragma unroll
                for (int nf2 = 0; nf2 < 2; nf2++)
                    #pragma unroll
                    for (int j = 0; j < 2; j++) {
                        float* a4 = acc[mf][nf2 * 2 + j];
                        mma_bf16(a4, ah[mf], bh[nf2][2 * j], bh[nf2][2 * j + 1]);
                        mma_bf16(a4, al[mf], bh[nf2][2 * j], bh[nf2][2 * j + 1]);
                        mma_bf16(a4, ah[mf], bl[nf2][2 * j], bl[nf2][2 * j + 1]);
                    }
        }
        __syncthreads();
    }

    // Epilogue
    const int gid = lane >> 2, tig = lane & 3;
    #pragma unroll
    for (int mf = 0; mf < 4; mf++) {
        #pragma unroll
        for (int nf = 0; nf < 4; nf++) {
            const int n = bn + wn * 32 + nf * 8 + 2 * tig;
            const float bx = bias[n], by = bias[n + 1];
            #pragma unroll
            for (int h = 0; h < 2; h++) {
                const int row = bm + wm * 64 + mf * 16 + gid + h * 8;
                float2 cv;
                cv.x = acc[mf][nf][2 * h + 0] + bx;
                cv.y = acc[mf][nf][2 * h + 1] + by;
                if (!kv_out) {
                    *(float2*)&C[(size_t)row * N + n] = cv;
                } else if (n < 1024) {               // q: scale + split bf16
                    float x = cv.x * 0.125f, y = cv.y * 0.125f;
                    __nv_bfloat16 h0 = __float2bfloat16(x), h1 = __float2bfloat16(y);
                    *(__nv_bfloat162*)&qhi[(size_t)row * DMODEL + n] = __halves2bfloat162(h0, h1);
                    *(__nv_bfloat162*)&qlo[(size_t)row * DMODEL + n] =
                        __halves2bfloat162(__float2bfloat16(x - __bfloat162float(h0)),
                                           __float2bfloat16(y - __bfloat162float(h1)));
                } else if (n < 2048) {               // k: split bf16 + fp32 out
                    const int nk = n - 1024;
                    __nv_bfloat16 h0 = __float2bfloat16(cv.x), h1 = __float2bfloat16(cv.y);
                    *(__nv_bfloat162*)&khi[(size_t)row * DMODEL + nk] = __halves2bfloat162(h0, h1);
                    *(__nv_bfloat162*)&klo[(size_t)row * DMODEL + nk] =
                        __halves2bfloat162(__float2bfloat16(cv.x - __bfloat162float(h0)),
                                           __float2bfloat16(cv.y - __bfloat162float(h1)));
                    *(float2*)&kv_out[(size_t)row * DMODEL + nk] = cv;
                } else {                             // v: fp16 + fp32 out
                    const int nv = n - 2048;
                    *(__half2*)&vh[(size_t)row * DMODEL + nv] = __floats2half2_rn(cv.x, cv.y);
                    *(float2*)&kv_out[(size_t)OUT_ELEMS + (size_t)row * DMODEL + nv] = cv;
                }
            }
        }
    }
}

// ---------------------------------------------------------------------------
// Causal flash attention on mma.sync.
// CTA: 128 q-rows x (64-token kv tiles), 8 warps each own m16, full n width.
// S = Qhi*Khi + Qlo*Khi + Qhi*Klo (bf16 split, fp32 acc); O += P(f16) * V(f16).
// smem rows stride 144 B (72 halves) -> conflict-free ldmatrix.
// ---------------------------------------------------------------------------
#define FQ0    0
#define FQ1    (128 * 144)           // 18432
#define FSTG   (2 * 128 * 144)       // 36864
#define FKHI   0
#define FKLO   9216
#define FV     18432
#define FSTGB  27648
#define FL_SMEM (FSTG + 2 * FSTGB)   // 92160

__global__ __launch_bounds__(256)
void flash_mma(const __nv_bfloat16* __restrict__ qhi, const __nv_bfloat16* __restrict__ qlo,
               const __nv_bfloat16* __restrict__ khi, const __nv_bfloat16* __restrict__ klo,
               const __half* __restrict__ vh, float* __restrict__ out)
{
    extern __shared__ __align__(128) char smf[];
    const uint32_t sb = smem_u32(smf);
    const int tid = threadIdx.x, wid = tid >> 5, lane = tid & 31;
    const int qt = (int)gridDim.x - 1 - (int)blockIdx.x;   // long blocks first
    const int h = blockIdx.y, b = blockIdx.z;
    const int bq0 = qt * 128;
    const int nkv = 2 * (qt + 1);
    const size_t tokbase = (size_t)b * SEQ;
    const int hoff = h * DHEAD;

    // Q tiles (hi, lo) -> smem
    #pragma unroll
    for (int i = 0; i < 4; i++) {
        const int idx = tid + 256 * i;                 // 0..1023
        const int row = idx >> 3, q = idx & 7;
        const size_t g = (tokbase + bq0 + row) * DMODEL + hoff + q * 8;
        CPASYNC16(sb + FQ0 + row * 144 + q * 16, (const char*)(qhi + g));
        CPASYNC16(sb + FQ1 + row * 144 + q * 16, (const char*)(qlo + g));
    }

    auto load_kv = [&](int c, int s) {
        const size_t rb = tokbase + c * 64;
        const uint32_t st = sb + FSTG + s * FSTGB;
        #pragma unroll
        for (int i = 0; i < 2; i++) {
            const int idx = tid + 256 * i;             // 0..511
            const int row = idx >> 3, q = idx & 7;
            const size_t g = (rb + row) * DMODEL + hoff + q * 8;
            CPASYNC16(st + FKHI + row * 144 + q * 16, (const char*)(khi + g));
            CPASYNC16(st + FKLO + row * 144 + q * 16, (const char*)(klo + g));
            CPASYNC16(st + FV   + row * 144 + q * 16, (const char*)(vh  + g));
        }
        CPCOMMIT();
    };
    load_kv(0, 0);   // group 0 = Q + kv stage 0

    const int a_row = (lane & 15);
    const int a_kb  = ((lane >> 4) << 3) * 2;
    const int b_row = ((lane >> 4) << 3) + (lane & 7);
    const int b_kb  = (((lane >> 3) & 1) << 3) * 2;
    const int gid = lane >> 2, tig = lane & 3;

    const int wrow0 = bq0 + wid * 16;                  // warp min row
    const int r0 = wrow0 + gid, r1 = r0 + 8;           // this lane's rows

    uint32_t qh_[4][4], ql_[4][4];
    float o_[8][4];
    #pragma unroll
    for (int i = 0; i < 8; i++)
        #pragma unroll
        for (int j = 0; j < 4; j++) o_[i][j] = 0.f;
    float m0 = -1e30f, m1 = -1e30f, l0 = 0.f, l1 = 0.f;
    bool qloaded = false;

    #pragma unroll 1
    for (int c = 0; c < nkv; c++) {
        const int s = c & 1;
        if (c + 1 < nkv) {
            load_kv(c + 1, s ^ 1);
            asm volatile("cp.async.wait_group 1;" ::: "memory");
        } else {
            asm volatile("cp.async.wait_group 0;" ::: "memory");
        }
        __syncthreads();

        if (!qloaded) {
            qloaded = true;
            const uint32_t off = (uint32_t)(wid * 16 + a_row) * 144 + a_kb;
            #pragma unroll
            for (int kf = 0; kf < 4; kf++) {
                ldx4(qh_[kf], sb + FQ0 + off + kf * 32);
                ldx4(ql_[kf], sb + FQ1 + off + kf * 32);
            }
        }

        const int kv0 = c * 64;
        if (kv0 <= wrow0 + 15) {                       // not fully masked for warp
            const uint32_t st = sb + FSTG + s * FSTGB;

            // S = Q K^T (split bf16)
            float s_[8][4];
            #pragma unroll
            for (int i = 0; i < 8; i++)
                #pragma unroll
                for (int j = 0; j < 4; j++) s_[i][j] = 0.f;
            #pragma unroll
            for (int kf = 0; kf < 4; kf++) {
                #pragma unroll
                for (int nf2 = 0; nf2 < 4; nf2++) {
                    uint32_t bh[4], bl[4];
                    const uint32_t off = (uint32_t)(nf2 * 16 + b_row) * 144 + b_kb + kf * 32;
                    ldx4(bh, st + FKHI + off);
                    ldx4(bl, st + FKLO + off);
                    #pragma unroll
                    for (int j = 0; j < 2; j++) {
                        float* a4 = s_[nf2 * 2 + j];
                        mma_bf16(a4, qh_[kf], bh[2 * j], bh[2 * j + 1]);
                        mma_bf16(a4, ql_[kf], bh[2 * j], bh[2 * j + 1]);
                        mma_bf16(a4, qh_[kf], bl[2 * j], bl[2 * j + 1]);
                    }
                }
            }

            // causal mask (only near the diagonal)
            if (kv0 + 63 > wrow0) {
                #pragma unroll
                for (int nf = 0; nf < 8; nf++)
                    #pragma unroll
                    for (int e = 0; e < 2; e++) {
                        const int col = kv0 + 8 * nf + 2 * tig + e;
                        if (col > r0) s_[nf][e]     = -1e30f;
                        if (col > r1) s_[nf][2 + e] = -1e30f;
                    }
            }

            // online softmax (quad-lane reductions)
            float mx0 = -1e30f, mx1 = -1e30f;
            #pragma unroll
            for (int nf = 0; nf < 8; nf++) {
                mx0 = fmaxf(mx0, fmaxf(s_[nf][0], s_[nf][1]));
                mx1 = fmaxf(mx1, fmaxf(s_[nf][2], s_[nf][3]));
            }
            mx0 = fmaxf(mx0, __shfl_xor_sync(0xffffffffu, mx0, 1));
            mx0 = fmaxf(mx0, __shfl_xor_sync(0xffffffffu, mx0, 2));
            mx1 = fmaxf(mx1, __shfl_xor_sync(0xffffffffu, mx1, 1));
            mx1 = fmaxf(mx1, __shfl_xor_sync(0xffffffffu, mx1, 2));
            const float mn0 = fmaxf(m0, mx0), mn1 = fmaxf(m1, mx1);
            const float sc0 = __expf(m0 - mn0), sc1 = __expf(m1 - mn1);
            float rs0 = 0.f, rs1 = 0.f;
            #pragma unroll
            for (int nf = 0; nf < 8; nf++) {
                s_[nf][0] = __expf(s_[nf][0] - mn0); rs0 += s_[nf][0];
                s_[nf][1] = __expf(s_[nf][1] - mn0); rs0 += s_[nf][1];
                s_[nf][2] = __expf(s_[nf][2] - mn1); rs1 += s_[nf][2];
                s_[nf][3] = __expf(s_[nf][3] - mn1); rs1 += s_[nf][3];
            }
            rs0 += __shfl_xor_sync(0xffffffffu, rs0, 1);
            rs0 += __shfl_xor_sync(0xffffffffu, rs0, 2);
            rs1 += __shfl_xor_sync(0xffffffffu, rs1, 1);
            rs1 += __shfl_xor_sync(0xffffffffu, rs1, 2);
            l0 = l0 * sc0 + rs0; m0 = mn0;
            l1 = l1 * sc1 + rs1; m1 = mn1;
            #pragma unroll
            for (int nf = 0; nf < 8; nf++) {
                o_[nf][0] *= sc0; o_[nf][1] *= sc0;
                o_[nf][2] *= sc1; o_[nf][3] *= sc1;
            }

            // O += P V  (P from regs, V^T via ldmatrix.trans)
            #pragma unroll
            for (int kg = 0; kg < 4; kg++) {
                uint32_t pa[4];
                pa[0] = packh2(s_[2 * kg][0],     s_[2 * kg][1]);
                pa[1] = packh2(s_[2 * kg][2],     s_[2 * kg][3]);
                pa[2] = packh2(s_[2 * kg + 1][0], s_[2 * kg + 1][1]);
                pa[3] = packh2(s_[2 * kg + 1][2], s_[2 * kg + 1][3]);
                #pragma unroll
                for (int nf2 = 0; nf2 < 4; nf2++) {
                    uint32_t bv[4];
                    const uint32_t voff = (uint32_t)(kg * 16 + (lane & 15)) * 144
                                        + (uint32_t)(nf2 * 16 + (lane >> 4) * 8) * 2;
                    ldx4t(bv, st + FV + voff);
                    mma_f16(o_[nf2 * 2],     pa, bv[0], bv[1]);
                    mma_f16(o_[nf2 * 2 + 1], pa, bv[2], bv[3]);
                }
            }
        }
        __syncthreads();
    }

    // normalize + store to att [row][h*64 + n]
    const float inv0 = 1.0f / l0, inv1 = 1.0f / l1;
    #pragma unroll
    for (int nf = 0; nf < 8; nf++) {
        const int n = hoff + 8 * nf + 2 * tig;
        float2 v0 = make_float2(o_[nf][0] * inv0, o_[nf][1] * inv0);
        float2 v1 = make_float2(o_[nf][2] * inv1, o_[nf][3] * inv1);
        *(float2*)&out[(tokbase + r0) * DMODEL + n] = v0;
        *(float2*)&out[(tokbase + r1) * DMODEL + n] = v1;
    }
}

// ---------------------------------------------------------------------------
extern "C" void kernel_launch(void* const* d_in, const int* in_sizes, int n_in,
                              void* d_out, int out_size)
{
    const float* input = (const float*)d_in[0];
    // d_in[1] = mask (causal, hardcoded — ignored)
    const float* W_qkv = (const float*)d_in[2];
    const float* b_qkv = (const float*)d_in[3];
    const float* W_out = (const float*)d_in[4];
    const float* b_out = (const float*)d_in[5];
    float* out = (float*)d_out;

    float* att_ptr = nullptr;
    __nv_bfloat16 *ahi, *alo, *bhi, *blo, *qhi, *qlo, *khi, *klo;
    __half* vh;
    cudaGetSymbolAddress((void**)&att_ptr, g_att);
    cudaGetSymbolAddress((void**)&ahi, g_Ahi);
    cudaGetSymbolAddress((void**)&alo, g_Alo);
    cudaGetSymbolAddress((void**)&bhi, g_Bhi);
    cudaGetSymbolAddress((void**)&blo, g_Blo);
    cudaGetSymbolAddress((void**)&qhi, g_qhi);
    cudaGetSymbolAddress((void**)&qlo, g_qlo);
    cudaGetSymbolAddress((void**)&khi, g_khi);
    cudaGetSymbolAddress((void**)&klo, g_klo);
    cudaGetSymbolAddress((void**)&vh,  g_vh);

    float* kv_out = out + OUT_ELEMS;   // (out, k, v) layout

    cudaFuncSetAttribute(gemm_mma, cudaFuncAttributeMaxDynamicSharedMemorySize, GM_SMEM);
    cudaFuncSetAttribute(flash_mma, cudaFuncAttributeMaxDynamicSharedMemorySize, FL_SMEM);

    // 1) split input + W_qkv^T to bf16 hi/lo
    convert_hi_lo<<<(OUT_ELEMS / 4 + 255) / 256, 256>>>(input, ahi, alo, OUT_ELEMS / 4);
    convert_wt<<<dim3(NQKV / 32, DMODEL / 32), dim3(32, 8)>>>(W_qkv, bhi, blo, NQKV);

    // 2) QKV gemm -> q/k split bf16, v fp16, k/v fp32 to output
    gemm_mma<<<dim3(NQKV / 128, MROWS / 128), 256, GM_SMEM>>>(
        ahi, alo, bhi, blo, b_qkv, nullptr, NQKV, kv_out,
        qhi, qlo, khi, klo, vh);

    // 3) causal flash attention (tensor cores)
    flash_mma<<<dim3(SEQ / 128, NHEAD, BATCH), 256, FL_SMEM>>>(
        qhi, qlo, khi, klo, vh, att_ptr);

    // 4) split att + W_out^T, then out = att @ W_out + b_out
    convert_hi_lo<<<(OUT_ELEMS / 4 + 255) / 256, 256>>>(att_ptr, ahi, alo, OUT_ELEMS / 4);
    convert_wt<<<dim3(DMODEL / 32, DMODEL / 32), dim3(32, 8)>>>(W_out, bhi, blo, DMODEL);
    gemm_mma<<<dim3(DMODEL / 128, MROWS / 128), 256, GM_SMEM>>>(
        ahi, alo, bhi, blo, b_out, out, DMODEL, nullptr,
        nullptr, nullptr, nullptr, nullptr, nullptr);
}